// round 1
// baseline (speedup 1.0000x reference)
#include <cuda_runtime.h>
#include <math.h>

// Problem constants
#define NQ 512
#define NC 65536
#define D  768
#define PD 64          // packed projection dim: e[0:32) h[32:48) s[48:64)

// Scratch (no allocations allowed)
__device__ float g_c[(size_t)NC * PD];   // corpus projections, row-major [row][64]
__device__ float g_cyn[NC];              // ||c_h||^2 = tanh^2(n)
__device__ float g_q[(size_t)NQ * PD];   // query projections
__device__ float g_qxn[NQ];              // ||q_h||^2
__device__ float g_qw[(size_t)NQ * 3];   // softplus weights

// ---------------------------------------------------------------------------
// Kernel 1: query projections + weight MLP. One block per query, 128 threads.
// ---------------------------------------------------------------------------
__global__ __launch_bounds__(128) void proj_q_kernel(
    const float* __restrict__ xq,
    const float* __restrict__ We, const float* __restrict__ be,
    const float* __restrict__ Wh, const float* __restrict__ bh,
    const float* __restrict__ Ws, const float* __restrict__ bs,
    const float* __restrict__ scale_h_p,
    const float* __restrict__ W1, const float* __restrict__ b1,
    const float* __restrict__ W2, const float* __restrict__ b2)
{
    __shared__ float xs[D];
    __shared__ float buf[96];
    const int q   = blockIdx.x;
    const int tid = threadIdx.x;

    const float* xrow = xq + (size_t)q * D;
    for (int i = tid; i < D; i += 128) xs[i] = xrow[i];
    __syncthreads();

    if (tid < 96) {
        const float* wrow;
        float bias;
        if (tid < 32)      { wrow = We + (size_t)tid * D;       bias = be[tid]; }
        else if (tid < 48) { wrow = Wh + (size_t)(tid-32) * D;  bias = bh[tid-32]; }
        else if (tid < 64) { wrow = Ws + (size_t)(tid-48) * D;  bias = bs[tid-48]; }
        else               { wrow = W1 + (size_t)(tid-64) * D;  bias = b1[tid-64]; }
        float acc = bias;
        #pragma unroll 8
        for (int k = 0; k < D; k++) acc = fmaf(wrow[k], xs[k], acc);
        buf[tid] = acc;
    }
    __syncthreads();

    const int warp = tid >> 5, lane = tid & 31;
    if (warp == 0) {
        // e: 32 dims, normalize
        float v  = buf[lane];
        float ss = v * v;
        #pragma unroll
        for (int o = 16; o; o >>= 1) ss += __shfl_xor_sync(0xffffffffu, ss, o);
        g_q[(size_t)q * PD + lane] = v * rsqrtf(ss);
    } else if (warp == 1) {
        // lanes 0-15: h (expmap0 with scale), lanes 16-31: s (normalize)
        const float sc = *scale_h_p;
        float v = (lane < 16) ? buf[32 + lane] * sc : buf[32 + lane];
        float ss = v * v;
        #pragma unroll
        for (int o = 8; o; o >>= 1) ss += __shfl_xor_sync(0xffffffffu, ss, o);
        if (lane < 16) {
            float n  = fmaxf(sqrtf(ss), 1e-15f);
            float th = tanhf(n);
            g_q[(size_t)q * PD + 32 + lane] = v * (th / n);
            if (lane == 0) g_qxn[q] = th * th;
        } else {
            g_q[(size_t)q * PD + 32 + lane] = v * rsqrtf(ss); // 48 + (lane-16)
        }
    } else if (warp == 2) {
        // weight MLP: relu -> 3 dots over 32 -> softplus
        float h = fmaxf(buf[64 + lane], 0.0f);
        #pragma unroll
        for (int i = 0; i < 3; i++) {
            float p = h * W2[i * 32 + lane];
            #pragma unroll
            for (int o = 16; o; o >>= 1) p += __shfl_xor_sync(0xffffffffu, p, o);
            if (lane == 0) {
                float z  = p + b2[i];
                float sp = fmaxf(z, 0.0f) + log1pf(expf(-fabsf(z)));
                g_qw[(size_t)q * 3 + i] = sp;
            }
        }
    }
}

// ---------------------------------------------------------------------------
// Kernel 2: corpus projection GEMM [NC,768]x[768,64] + fused epilogue.
// Block: 64 rows x 64 cols, 256 threads, 4x4 register tile, BK=16.
// ---------------------------------------------------------------------------
#define BK 16
__global__ __launch_bounds__(256) void proj_c_kernel(
    const float* __restrict__ xc,
    const float* __restrict__ We, const float* __restrict__ be,
    const float* __restrict__ Wh, const float* __restrict__ bh,
    const float* __restrict__ Ws, const float* __restrict__ bs,
    const float* __restrict__ scale_h_p)
{
    __shared__ float xs[BK][68];    // [k][row]
    __shared__ float wsm[BK][68];   // [k][col]
    __shared__ float ob[64][68];    // staged outputs
    __shared__ float bias_s[64];

    const int tid  = threadIdx.x;
    const int row0 = blockIdx.x * 64;

    if (tid < 64) {
        float b;
        if (tid < 32)      b = be[tid];
        else if (tid < 48) b = bh[tid - 32];
        else               b = bs[tid - 48];
        bias_s[tid] = b;
    }

    // loading roles
    const int lr  = tid >> 2;          // row / col index 0..63
    const int lk4 = (tid & 3) * 4;     // k offset within chunk
    const float* wrow;
    if (lr < 32)      wrow = We + (size_t)lr * D;
    else if (lr < 48) wrow = Wh + (size_t)(lr - 32) * D;
    else              wrow = Ws + (size_t)(lr - 48) * D;

    // compute roles
    const int tr = (tid >> 4) * 4;     // tile row
    const int tc = (tid & 15) * 4;     // tile col

    float acc[4][4] = {};
    const float* xbase = xc + (size_t)row0 * D;

    for (int kk = 0; kk < D; kk += BK) {
        float4 xv = *(const float4*)(xbase + (size_t)lr * D + kk + lk4);
        float4 wv = *(const float4*)(wrow + kk + lk4);
        __syncthreads();
        xs[lk4+0][lr] = xv.x; xs[lk4+1][lr] = xv.y;
        xs[lk4+2][lr] = xv.z; xs[lk4+3][lr] = xv.w;
        wsm[lk4+0][lr] = wv.x; wsm[lk4+1][lr] = wv.y;
        wsm[lk4+2][lr] = wv.z; wsm[lk4+3][lr] = wv.w;
        __syncthreads();
        #pragma unroll
        for (int k = 0; k < BK; k++) {
            float4 a = *(const float4*)&xs[k][tr];
            float4 b = *(const float4*)&wsm[k][tc];
            float av[4] = {a.x, a.y, a.z, a.w};
            float bv[4] = {b.x, b.y, b.z, b.w};
            #pragma unroll
            for (int i = 0; i < 4; i++)
                #pragma unroll
                for (int j = 0; j < 4; j++)
                    acc[i][j] = fmaf(av[i], bv[j], acc[i][j]);
        }
    }

    #pragma unroll
    for (int i = 0; i < 4; i++)
        #pragma unroll
        for (int j = 0; j < 4; j++)
            ob[tr + i][tc + j] = acc[i][j];
    __syncthreads();

    // epilogue: 4 threads per row; part 0,1 -> e, part 2 -> h, part 3 -> s
    const int r = tid >> 2, part = tid & 3;
    const float sc = *scale_h_p;
    float vals[16];
    float ss = 0.0f;
    const int cbase = part * 16;
    #pragma unroll
    for (int j = 0; j < 16; j++) {
        float v = ob[r][cbase + j] + bias_s[cbase + j];
        if (part == 2) v *= sc;
        vals[j] = v;
        ss += v * v;
    }
    float other = __shfl_xor_sync(0xffffffffu, ss, 1);
    float seg   = (part < 2) ? (ss + other) : ss;

    const int grow = row0 + r;
    float* orow = g_c + (size_t)grow * PD + cbase;
    if (part == 2) {
        float n  = fmaxf(sqrtf(seg), 1e-15f);
        float th = tanhf(n);
        float f  = th / n;
        #pragma unroll
        for (int j = 0; j < 16; j++) orow[j] = vals[j] * f;
        g_cyn[grow] = th * th;
    } else {
        float inv = rsqrtf(seg);
        #pragma unroll
        for (int j = 0; j < 16; j++) orow[j] = vals[j] * inv;
    }
}

// ---------------------------------------------------------------------------
// Kernel 3: pairwise distances + weighted combine.
// Block: 64 queries x 64 corpus, 256 threads, 4x4 register tile, full K=64.
// ---------------------------------------------------------------------------
__global__ __launch_bounds__(256) void pairwise_kernel(float* __restrict__ out)
{
    __shared__ float qs[64][68];   // [k][q]
    __shared__ float cs[64][68];   // [k][c]
    __shared__ float sqxn[64];
    __shared__ float sqw[64][3];
    __shared__ float scyn[64];

    const int tid   = threadIdx.x;
    const int c0blk = blockIdx.x * 64;
    const int q0blk = blockIdx.y * 64;

    // load tiles transposed (float4 global reads)
    #pragma unroll
    for (int i = 0; i < 4; i++) {
        int f4  = tid + i * 256;         // 0..1023
        int row = f4 >> 4;               // 0..63
        int k4  = (f4 & 15) * 4;
        float4 v = *(const float4*)(g_q + (size_t)(q0blk + row) * PD + k4);
        qs[k4+0][row] = v.x; qs[k4+1][row] = v.y;
        qs[k4+2][row] = v.z; qs[k4+3][row] = v.w;
        float4 w = *(const float4*)(g_c + (size_t)(c0blk + row) * PD + k4);
        cs[k4+0][row] = w.x; cs[k4+1][row] = w.y;
        cs[k4+2][row] = w.z; cs[k4+3][row] = w.w;
    }
    if (tid < 64) {
        sqxn[tid]   = g_qxn[q0blk + tid];
        scyn[tid]   = g_cyn[c0blk + tid];
        sqw[tid][0] = g_qw[(size_t)(q0blk + tid) * 3 + 0];
        sqw[tid][1] = g_qw[(size_t)(q0blk + tid) * 3 + 1];
        sqw[tid][2] = g_qw[(size_t)(q0blk + tid) * 3 + 2];
    }
    __syncthreads();

    const int tq0 = (tid >> 4) * 4;
    const int tc0 = (tid & 15) * 4;

    float ae[16] = {}, ah[16] = {}, asx[16] = {};

    #pragma unroll
    for (int k = 0; k < 32; k++) {
        float4 a = *(const float4*)&qs[k][tq0];
        float4 b = *(const float4*)&cs[k][tc0];
        float av[4] = {a.x, a.y, a.z, a.w};
        float bv[4] = {b.x, b.y, b.z, b.w};
        #pragma unroll
        for (int i = 0; i < 4; i++)
            #pragma unroll
            for (int j = 0; j < 4; j++)
                ae[i*4+j] = fmaf(av[i], bv[j], ae[i*4+j]);
    }
    #pragma unroll
    for (int k = 32; k < 48; k++) {
        float4 a = *(const float4*)&qs[k][tq0];
        float4 b = *(const float4*)&cs[k][tc0];
        float av[4] = {a.x, a.y, a.z, a.w};
        float bv[4] = {b.x, b.y, b.z, b.w};
        #pragma unroll
        for (int i = 0; i < 4; i++)
            #pragma unroll
            for (int j = 0; j < 4; j++)
                ah[i*4+j] = fmaf(av[i], bv[j], ah[i*4+j]);
    }
    #pragma unroll
    for (int k = 48; k < 64; k++) {
        float4 a = *(const float4*)&qs[k][tq0];
        float4 b = *(const float4*)&cs[k][tc0];
        float av[4] = {a.x, a.y, a.z, a.w};
        float bv[4] = {b.x, b.y, b.z, b.w};
        #pragma unroll
        for (int i = 0; i < 4; i++)
            #pragma unroll
            for (int j = 0; j < 4; j++)
                asx[i*4+j] = fmaf(av[i], bv[j], asx[i*4+j]);
    }

    #pragma unroll
    for (int i = 0; i < 4; i++) {
        const int q   = tq0 + i;
        const float xn = sqxn[q];
        const float w0 = sqw[q][0], w1 = sqw[q][1], w2 = sqw[q][2];
        const float beta = 1.0f - xn;
        float4 res;
        float rv[4];
        #pragma unroll
        for (int j = 0; j < 4; j++) {
            const float yn = scyn[tc0 + j];
            // Euclidean (unit vectors)
            float de = 2.0f - 2.0f * ae[i*4+j];
            // Spherical
            float dots = fminf(fmaxf(asx[i*4+j], -1.0f + 1e-7f), 1.0f - 1e-7f);
            float acs  = acosf(dots);
            float ds   = acs * acs;
            // Hyperbolic (Poincare, c=1)
            float dt    = ah[i*4+j];
            float alpha = 1.0f - 2.0f * dt + yn;
            float nsq   = alpha*alpha*xn - 2.0f*alpha*beta*dt + beta*beta*yn;
            float den   = fmaxf(1.0f - 2.0f*dt + xn*yn, 1e-15f);
            float t     = sqrtf(fmaxf(nsq, 0.0f)) / den;
            t = fminf(fmaxf(t, 0.0f), 1.0f - 1e-7f);
            float dd = 2.0f * atanhf(t);
            float dh = dd * dd;
            rv[j] = -(w0 * de + w1 * dh + w2 * ds);
        }
        res.x = rv[0]; res.y = rv[1]; res.z = rv[2]; res.w = rv[3];
        *(float4*)(out + (size_t)(q0blk + q) * NC + c0blk + tc0) = res;
    }
}

// ---------------------------------------------------------------------------
extern "C" void kernel_launch(void* const* d_in, const int* in_sizes, int n_in,
                              void* d_out, int out_size)
{
    const float* xq  = (const float*)d_in[0];
    const float* xc  = (const float*)d_in[1];
    const float* We  = (const float*)d_in[2];
    const float* be  = (const float*)d_in[3];
    const float* Wh  = (const float*)d_in[4];
    const float* bh  = (const float*)d_in[5];
    const float* Ws  = (const float*)d_in[6];
    const float* bs  = (const float*)d_in[7];
    const float* sh  = (const float*)d_in[8];
    const float* W1  = (const float*)d_in[9];
    const float* b1  = (const float*)d_in[10];
    const float* W2  = (const float*)d_in[11];
    const float* b2  = (const float*)d_in[12];
    float* out = (float*)d_out;

    proj_q_kernel<<<NQ, 128>>>(xq, We, be, Wh, bh, Ws, bs, sh, W1, b1, W2, b2);
    proj_c_kernel<<<NC / 64, 256>>>(xc, We, be, Wh, bh, Ws, bs, sh);
    pairwise_kernel<<<dim3(NC / 64, NQ / 64), 256>>>(out);
}

// round 5
// speedup vs baseline: 1.4619x; 1.4619x over previous
#include <cuda_runtime.h>
#include <math.h>

// Problem constants
#define NQ 512
#define NC 65536
#define D  768
#define PD 64          // packed projection dim: e[0:32) h[32:48) s[48:64)

#define NCBLK (NC / 64)   // 1024 corpus blocks
#define NQBLK (NQ / 64)   // 8 query blocks

typedef unsigned long long u64;

// packed-fp32 helpers (sm_103a f32x2 pipe — 2x FFMA throughput, exact fp32)
__device__ __forceinline__ u64 pack2(float v) {
    u64 r;
    asm("mov.b64 %0, {%1, %1};" : "=l"(r) : "f"(v));
    return r;
}
__device__ __forceinline__ void fma2(u64& d, u64 a, u64 b) {
    asm("fma.rn.f32x2 %0, %1, %2, %0;" : "+l"(d) : "l"(a), "l"(b));
}
__device__ __forceinline__ void unpack2(float& lo, float& hi, u64 v) {
    asm("mov.b64 {%0, %1}, %2;" : "=f"(lo), "=f"(hi) : "l"(v));
}

// Scratch (no allocations allowed)
__device__ float g_c[(size_t)NC * PD];   // corpus projections, row-major [row][64]
__device__ float g_cyn[NC];              // ||c_h||^2 = tanh^2(n)
__device__ float g_q[(size_t)NQ * PD];   // query projections
__device__ float g_qxn[NQ];              // ||q_h||^2
__device__ float g_qw[(size_t)NQ * 3];   // softplus weights

// ---------------------------------------------------------------------------
// Kernel 1: weight MLP. One block per query, 8 warps x 4 hidden units.
// ---------------------------------------------------------------------------
__global__ __launch_bounds__(256) void mlp_kernel(
    const float* __restrict__ xq,
    const float* __restrict__ W1, const float* __restrict__ b1,
    const float* __restrict__ W2, const float* __restrict__ b2)
{
    __shared__ float xs[D];
    __shared__ float hid[32];

    const int q    = blockIdx.x;
    const int tid  = threadIdx.x;
    const int warp = tid >> 5, lane = tid & 31;

    const float4* xrow4 = (const float4*)(xq + (size_t)q * D);
    if (tid < D / 4) ((float4*)xs)[tid] = xrow4[tid];
    __syncthreads();

    float acc0 = 0.f, acc1 = 0.f, acc2 = 0.f, acc3 = 0.f;
    const float* w0  = W1 + (size_t)(warp * 4 + 0) * D;
    const float* w1r = W1 + (size_t)(warp * 4 + 1) * D;
    const float* w2r = W1 + (size_t)(warp * 4 + 2) * D;
    const float* w3r = W1 + (size_t)(warp * 4 + 3) * D;
    #pragma unroll 4
    for (int k = lane; k < D; k += 32) {
        float xv = xs[k];
        acc0 = fmaf(w0[k],  xv, acc0);
        acc1 = fmaf(w1r[k], xv, acc1);
        acc2 = fmaf(w2r[k], xv, acc2);
        acc3 = fmaf(w3r[k], xv, acc3);
    }
    #pragma unroll
    for (int o = 16; o; o >>= 1) {
        acc0 += __shfl_xor_sync(0xffffffffu, acc0, o);
        acc1 += __shfl_xor_sync(0xffffffffu, acc1, o);
        acc2 += __shfl_xor_sync(0xffffffffu, acc2, o);
        acc3 += __shfl_xor_sync(0xffffffffu, acc3, o);
    }
    if (lane == 0) {
        hid[warp * 4 + 0] = fmaxf(acc0 + b1[warp * 4 + 0], 0.0f);
        hid[warp * 4 + 1] = fmaxf(acc1 + b1[warp * 4 + 1], 0.0f);
        hid[warp * 4 + 2] = fmaxf(acc2 + b1[warp * 4 + 2], 0.0f);
        hid[warp * 4 + 3] = fmaxf(acc3 + b1[warp * 4 + 3], 0.0f);
    }
    __syncthreads();

    if (warp == 0) {
        float h = hid[lane];
        #pragma unroll
        for (int i = 0; i < 3; i++) {
            float p = h * W2[i * 32 + lane];
            #pragma unroll
            for (int o = 16; o; o >>= 1) p += __shfl_xor_sync(0xffffffffu, p, o);
            if (lane == 0) {
                float z  = p + b2[i];
                float sp = fmaxf(z, 0.0f) + log1pf(expf(-fabsf(z)));
                g_qw[(size_t)q * 3 + i] = sp;
            }
        }
    }
}

// ---------------------------------------------------------------------------
// Kernel 2: projection GEMM [rows,768]x[768,64] + fused epilogue.
// Blocks 0..1023 -> corpus rows; blocks 1024..1031 -> query rows.
// 64x64 tile, 256 threads, 4x4 register tile via f32x2 packed FMA, BK=16.
// ---------------------------------------------------------------------------
#define BK 16
__global__ __launch_bounds__(256) void proj_kernel(
    const float* __restrict__ xc,
    const float* __restrict__ xq,
    const float* __restrict__ We, const float* __restrict__ be,
    const float* __restrict__ Wh, const float* __restrict__ bh,
    const float* __restrict__ Ws, const float* __restrict__ bs,
    const float* __restrict__ scale_h_p)
{
    __shared__ __align__(16) float xs[BK][68];    // [k][row]
    __shared__ __align__(16) float wsm[BK][68];   // [k][col]
    __shared__ __align__(16) float ob[64][68];    // staged outputs
    __shared__ float bias_s[64];

    const int tid = threadIdx.x;
    const int blk = blockIdx.x;
    const bool isQ = (blk >= NCBLK);
    const int  row0 = isQ ? (blk - NCBLK) * 64 : blk * 64;
    const float* xsrc = isQ ? xq : xc;
    float* gout = isQ ? g_q  : g_c;
    float* gyn  = isQ ? g_qxn : g_cyn;

    if (tid < 64) {
        float b;
        if (tid < 32)      b = be[tid];
        else if (tid < 48) b = bh[tid - 32];
        else               b = bs[tid - 48];
        bias_s[tid] = b;
    }

    // loading roles
    const int lr  = tid >> 2;          // row / col index 0..63
    const int lk4 = (tid & 3) * 4;     // k offset within chunk
    const float* wrow;
    if (lr < 32)      wrow = We + (size_t)lr * D;
    else if (lr < 48) wrow = Wh + (size_t)(lr - 32) * D;
    else              wrow = Ws + (size_t)(lr - 48) * D;

    // compute roles
    const int tr = (tid >> 4) * 4;     // tile row
    const int tc = (tid & 15) * 4;     // tile col

    u64 acc2[4][2] = {};               // 4 rows x 2 packed col-pairs
    const float* xbase = xsrc + (size_t)row0 * D;

    for (int kk = 0; kk < D; kk += BK) {
        float4 xv = *(const float4*)(xbase + (size_t)lr * D + kk + lk4);
        float4 wv = *(const float4*)(wrow + kk + lk4);
        __syncthreads();
        xs[lk4+0][lr] = xv.x; xs[lk4+1][lr] = xv.y;
        xs[lk4+2][lr] = xv.z; xs[lk4+3][lr] = xv.w;
        wsm[lk4+0][lr] = wv.x; wsm[lk4+1][lr] = wv.y;
        wsm[lk4+2][lr] = wv.z; wsm[lk4+3][lr] = wv.w;
        __syncthreads();
        #pragma unroll
        for (int k = 0; k < BK; k++) {
            float4 a = *(const float4*)&xs[k][tr];
            ulonglong2 b = *(const ulonglong2*)&wsm[k][tc];
            u64 ap0 = pack2(a.x), ap1 = pack2(a.y),
                ap2 = pack2(a.z), ap3 = pack2(a.w);
            fma2(acc2[0][0], ap0, b.x); fma2(acc2[0][1], ap0, b.y);
            fma2(acc2[1][0], ap1, b.x); fma2(acc2[1][1], ap1, b.y);
            fma2(acc2[2][0], ap2, b.x); fma2(acc2[2][1], ap2, b.y);
            fma2(acc2[3][0], ap3, b.x); fma2(acc2[3][1], ap3, b.y);
        }
    }

    #pragma unroll
    for (int i = 0; i < 4; i++) {
        float v0, v1, v2, v3;
        unpack2(v0, v1, acc2[i][0]);
        unpack2(v2, v3, acc2[i][1]);
        ob[tr + i][tc + 0] = v0; ob[tr + i][tc + 1] = v1;
        ob[tr + i][tc + 2] = v2; ob[tr + i][tc + 3] = v3;
    }
    __syncthreads();

    // epilogue: 4 threads per row; part 0,1 -> e, part 2 -> h, part 3 -> s
    const int r = tid >> 2, part = tid & 3;
    const float sc = *scale_h_p;
    float vals[16];
    float ss = 0.0f;
    const int cbase = part * 16;
    #pragma unroll
    for (int j = 0; j < 16; j++) {
        float v = ob[r][cbase + j] + bias_s[cbase + j];
        if (part == 2) v *= sc;
        vals[j] = v;
        ss += v * v;
    }
    float other = __shfl_xor_sync(0xffffffffu, ss, 1);
    float seg   = (part < 2) ? (ss + other) : ss;

    const int grow = row0 + r;
    float* orow = gout + (size_t)grow * PD + cbase;
    if (part == 2) {
        float n  = fmaxf(sqrtf(seg), 1e-15f);
        float th = tanhf(n);
        float f  = th / n;
        #pragma unroll
        for (int j = 0; j < 16; j++) orow[j] = vals[j] * f;
        gyn[grow] = th * th;
    } else {
        float inv = rsqrtf(seg);
        #pragma unroll
        for (int j = 0; j < 16; j++) orow[j] = vals[j] * inv;
    }
}

// ---------------------------------------------------------------------------
// Kernel 3: pairwise distances + weighted combine.
// 64x64 tile, 256 threads, 4x4 register tile via f32x2 packed FMA, K=64.
// ---------------------------------------------------------------------------
__global__ __launch_bounds__(256) void pairwise_kernel(float* __restrict__ out)
{
    __shared__ __align__(16) float qs[64][68];   // [k][q]
    __shared__ __align__(16) float cs[64][68];   // [k][c]
    __shared__ float sqxn[64];
    __shared__ float sqw[64][3];
    __shared__ float scyn[64];

    const int tid   = threadIdx.x;
    const int c0blk = blockIdx.x * 64;
    const int q0blk = blockIdx.y * 64;

    // load tiles transposed (float4 global reads)
    #pragma unroll
    for (int i = 0; i < 4; i++) {
        int f4  = tid + i * 256;         // 0..1023
        int row = f4 >> 4;               // 0..63
        int k4  = (f4 & 15) * 4;
        float4 v = *(const float4*)(g_q + (size_t)(q0blk + row) * PD + k4);
        qs[k4+0][row] = v.x; qs[k4+1][row] = v.y;
        qs[k4+2][row] = v.z; qs[k4+3][row] = v.w;
        float4 w = *(const float4*)(g_c + (size_t)(c0blk + row) * PD + k4);
        cs[k4+0][row] = w.x; cs[k4+1][row] = w.y;
        cs[k4+2][row] = w.z; cs[k4+3][row] = w.w;
    }
    if (tid < 64) {
        sqxn[tid]   = g_qxn[q0blk + tid];
        scyn[tid]   = g_cyn[c0blk + tid];
        sqw[tid][0] = g_qw[(size_t)(q0blk + tid) * 3 + 0];
        sqw[tid][1] = g_qw[(size_t)(q0blk + tid) * 3 + 1];
        sqw[tid][2] = g_qw[(size_t)(q0blk + tid) * 3 + 2];
    }
    __syncthreads();

    const int tq0 = (tid >> 4) * 4;
    const int tc0 = (tid & 15) * 4;

    u64 ae[4][2] = {}, ah[4][2] = {}, as2[4][2] = {};

    #pragma unroll
    for (int k = 0; k < 32; k++) {
        float4 a = *(const float4*)&qs[k][tq0];
        ulonglong2 b = *(const ulonglong2*)&cs[k][tc0];
        u64 ap0 = pack2(a.x), ap1 = pack2(a.y),
            ap2 = pack2(a.z), ap3 = pack2(a.w);
        fma2(ae[0][0], ap0, b.x); fma2(ae[0][1], ap0, b.y);
        fma2(ae[1][0], ap1, b.x); fma2(ae[1][1], ap1, b.y);
        fma2(ae[2][0], ap2, b.x); fma2(ae[2][1], ap2, b.y);
        fma2(ae[3][0], ap3, b.x); fma2(ae[3][1], ap3, b.y);
    }
    #pragma unroll
    for (int k = 32; k < 48; k++) {
        float4 a = *(const float4*)&qs[k][tq0];
        ulonglong2 b = *(const ulonglong2*)&cs[k][tc0];
        u64 ap0 = pack2(a.x), ap1 = pack2(a.y),
            ap2 = pack2(a.z), ap3 = pack2(a.w);
        fma2(ah[0][0], ap0, b.x); fma2(ah[0][1], ap0, b.y);
        fma2(ah[1][0], ap1, b.x); fma2(ah[1][1], ap1, b.y);
        fma2(ah[2][0], ap2, b.x); fma2(ah[2][1], ap2, b.y);
        fma2(ah[3][0], ap3, b.x); fma2(ah[3][1], ap3, b.y);
    }
    #pragma unroll
    for (int k = 48; k < 64; k++) {
        float4 a = *(const float4*)&qs[k][tq0];
        ulonglong2 b = *(const ulonglong2*)&cs[k][tc0];
        u64 ap0 = pack2(a.x), ap1 = pack2(a.y),
            ap2 = pack2(a.z), ap3 = pack2(a.w);
        fma2(as2[0][0], ap0, b.x); fma2(as2[0][1], ap0, b.y);
        fma2(as2[1][0], ap1, b.x); fma2(as2[1][1], ap1, b.y);
        fma2(as2[2][0], ap2, b.x); fma2(as2[2][1], ap2, b.y);
        fma2(as2[3][0], ap3, b.x); fma2(as2[3][1], ap3, b.y);
    }

    #pragma unroll
    for (int i = 0; i < 4; i++) {
        const int q    = tq0 + i;
        const float xn = sqxn[q];
        const float w0 = sqw[q][0], w1 = sqw[q][1], w2 = sqw[q][2];
        const float beta = 1.0f - xn;

        float ev[4], hv[4], sv[4];
        unpack2(ev[0], ev[1], ae[i][0]);  unpack2(ev[2], ev[3], ae[i][1]);
        unpack2(hv[0], hv[1], ah[i][0]);  unpack2(hv[2], hv[3], ah[i][1]);
        unpack2(sv[0], sv[1], as2[i][0]); unpack2(sv[2], sv[3], as2[i][1]);

        float rv[4];
        #pragma unroll
        for (int j = 0; j < 4; j++) {
            const float yn = scyn[tc0 + j];
            // Euclidean (unit vectors)
            float de = 2.0f - 2.0f * ev[j];
            // Spherical
            float dots = fminf(fmaxf(sv[j], -1.0f + 1e-7f), 1.0f - 1e-7f);
            float acs  = acosf(dots);
            float ds   = acs * acs;
            // Hyperbolic (Poincare, c=1)
            float dt    = hv[j];
            float alpha = 1.0f - 2.0f * dt + yn;
            float nsq   = alpha*alpha*xn - 2.0f*alpha*beta*dt + beta*beta*yn;
            float den   = fmaxf(1.0f - 2.0f*dt + xn*yn, 1e-15f);
            float t     = __fdividef(sqrtf(fmaxf(nsq, 0.0f)), den);
            t = fminf(fmaxf(t, 0.0f), 1.0f - 1e-7f);
            // 2*atanh(t) = ln((1+t)/(1-t))
            float dd = __logf(__fdividef(1.0f + t, 1.0f - t));
            float dh = dd * dd;
            rv[j] = -(w0 * de + w1 * dh + w2 * ds);
        }
        float4 res = {rv[0], rv[1], rv[2], rv[3]};
        *(float4*)(out + (size_t)(q0blk + q) * NC + c0blk + tc0) = res;
    }
}

// ---------------------------------------------------------------------------
extern "C" void kernel_launch(void* const* d_in, const int* in_sizes, int n_in,
                              void* d_out, int out_size)
{
    const float* xq  = (const float*)d_in[0];
    const float* xc  = (const float*)d_in[1];
    const float* We  = (const float*)d_in[2];
    const float* be  = (const float*)d_in[3];
    const float* Wh  = (const float*)d_in[4];
    const float* bh  = (const float*)d_in[5];
    const float* Ws  = (const float*)d_in[6];
    const float* bs  = (const float*)d_in[7];
    const float* sh  = (const float*)d_in[8];
    const float* W1  = (const float*)d_in[9];
    const float* b1  = (const float*)d_in[10];
    const float* W2  = (const float*)d_in[11];
    const float* b2  = (const float*)d_in[12];
    float* out = (float*)d_out;

    mlp_kernel<<<NQ, 256>>>(xq, W1, b1, W2, b2);
    proj_kernel<<<NCBLK + NQBLK, 256>>>(xc, xq, We, be, Wh, bh, Ws, bs, sh);
    pairwise_kernel<<<dim3(NC / 64, NQ / 64), 256>>>(out);
}